// round 3
// baseline (speedup 1.0000x reference)
#include <cuda_runtime.h>
#include <cstdint>

#define NN 100000
#define NE 1600000
#define DC 128
#define NL 3

// ---------------- scratch (device globals; no allocations allowed) ----------
__device__ float g_z [(size_t)NN * DC];
__device__ float g_t1[(size_t)NN * DC];
__device__ float g_t2[(size_t)NN * DC];
__device__ float g_stats[2 * DC];
__device__ float g_aff [2 * DC];

__device__ __forceinline__ uint32_t f2tf(float f)
{
    uint32_t u;
    asm("cvt.rna.tf32.f32 %0, %1;" : "=r"(u) : "f"(f));
    return u;
}

// ---------------- tiny utility kernels --------------------------------------
__global__ void k_zero_stats() { g_stats[threadIdx.x] = 0.f; }

template<bool AFF>
__global__ void k_affine(const float* __restrict__ in, float* __restrict__ out, int relu)
{
    int i = blockIdx.x * blockDim.x + threadIdx.x;
    const int n4 = NN * DC / 4;
    if (i >= n4) return;
    float4 v = __ldg((const float4*)in + i);
    if (AFF) {
        int c4 = i & (DC / 4 - 1);
        float4 a = *((const float4*)g_aff + c4);
        float4 c = *((const float4*)g_aff + DC / 4 + c4);
        v.x = fmaf(a.x, v.x, c.x);
        v.y = fmaf(a.y, v.y, c.y);
        v.z = fmaf(a.z, v.z, c.z);
        v.w = fmaf(a.w, v.w, c.w);
        if (relu) {
            v.x = fmaxf(v.x, 0.f); v.y = fmaxf(v.y, 0.f);
            v.z = fmaxf(v.z, 0.f); v.w = fmaxf(v.w, 0.f);
        }
    }
    ((float4*)out)[i] = v;
}

// ---------------- edge scatter-add -------------------------------------------
template<bool AFF>
__global__ void k_scatter(const float* __restrict__ h, const int* __restrict__ ei, int relu)
{
    int gt = blockIdx.x * blockDim.x + threadIdx.x;
    int e = gt >> 5;
    int lane = gt & 31;
    if (e >= NE) return;
    int src = __ldg(ei + e);
    int dst = __ldg(ei + NE + e);
    float4 v = __ldg((const float4*)(h + (size_t)src * DC) + lane);
    if (AFF) {
        float4 a = *((const float4*)g_aff + lane);
        float4 c = *((const float4*)g_aff + DC / 4 + lane);
        v.x = fmaf(a.x, v.x, c.x);
        v.y = fmaf(a.y, v.y, c.y);
        v.z = fmaf(a.z, v.z, c.z);
        v.w = fmaf(a.w, v.w, c.w);
        if (relu) {
            v.x = fmaxf(v.x, 0.f); v.y = fmaxf(v.y, 0.f);
            v.z = fmaxf(v.z, 0.f); v.w = fmaxf(v.w, 0.f);
        }
    }
    float* p = g_z + (size_t)dst * DC + lane * 4;
    asm volatile("red.global.add.v4.f32 [%0], {%1, %2, %3, %4};"
                 :: "l"(p), "f"(v.x), "f"(v.y), "f"(v.z), "f"(v.w) : "memory");
}

// ---------------- 3xTF32 tensor-core GEMM + bias + BN-stats ------------------
// acc += a_hi*b_hi + a_hi*b_lo + a_lo*b_hi  (fp32-class accuracy on tensor pipe)
// Tile 128x128, K processed in two 64-chunks; hi/lo tiles in smem.
// 8 warps (4x2), per warp 2(m)x8(n) m16n8k8 positions.
#define SAP 68   // smem pitch (floats) for 64-wide K chunks; 68%32=4 -> conflict-free

template<bool AFF>
__global__ void __launch_bounds__(256, 1)
k_gemm_tc(const float* __restrict__ A, const float* __restrict__ W,
          const float* __restrict__ bias, float* __restrict__ out, int nrows)
{
    extern __shared__ float sm[];
    uint32_t* sAh = (uint32_t*)sm;                       // [128][SAP]
    uint32_t* sAl = sAh + 128 * SAP;
    uint32_t* sBh = sAl + 128 * SAP;                     // [n][k] transposed
    uint32_t* sBl = sBh + 128 * SAP;
    float* sSum = (float*)(sBl + 128 * SAP);             // [128]
    float* sSq  = sSum + DC;

    const int t = threadIdx.x;
    const int blockRow = blockIdx.x * 128;

    if (t < DC) { sSum[t] = 0.f; sSq[t] = 0.f; }

    const int w    = t >> 5;
    const int lane = t & 31;
    const int grp  = lane >> 2;
    const int qid  = lane & 3;
    const int rm   = (w & 3) * 32;
    const int cn   = (w >> 2) * 64;

    float acc[2][8][4];
    #pragma unroll
    for (int mi = 0; mi < 2; mi++)
        #pragma unroll
        for (int nj = 0; nj < 8; nj++)
            #pragma unroll
            for (int q = 0; q < 4; q++)
                acc[mi][nj][q] = 0.f;

    for (int kc = 0; kc < 2; kc++) {
        // ---- W[k][n] chunk -> sB{h,l}[n][k_local], transposed ----
        #pragma unroll
        for (int i = 0; i < 8; i++) {
            int idx = i * 256 + t;               // float4 idx over 64x128 chunk
            int kl  = idx >> 5;                  // 0..63
            int n4  = (idx & 31) * 4;
            float4 v = __ldg((const float4*)W + (kc * 64 + kl) * 32 + (idx & 31));
            uint32_t hx = f2tf(v.x), hy = f2tf(v.y), hz = f2tf(v.z), hw = f2tf(v.w);
            sBh[(n4 + 0) * SAP + kl] = hx;
            sBh[(n4 + 1) * SAP + kl] = hy;
            sBh[(n4 + 2) * SAP + kl] = hz;
            sBh[(n4 + 3) * SAP + kl] = hw;
            sBl[(n4 + 0) * SAP + kl] = f2tf(v.x - __uint_as_float(hx));
            sBl[(n4 + 1) * SAP + kl] = f2tf(v.y - __uint_as_float(hy));
            sBl[(n4 + 2) * SAP + kl] = f2tf(v.z - __uint_as_float(hz));
            sBl[(n4 + 3) * SAP + kl] = f2tf(v.w - __uint_as_float(hw));
        }
        // ---- A chunk (fused affine+relu), zero-pad invalid rows ----
        #pragma unroll
        for (int i = 0; i < 8; i++) {
            int idx = i * 256 + t;               // float4 idx over 128x64 chunk
            int m   = idx >> 4;                  // 0..127
            int k4  = idx & 15;                  // 0..15 (float4 within chunk)
            int gm  = blockRow + m;
            float4 v = make_float4(0.f, 0.f, 0.f, 0.f);
            if (gm < nrows) {
                v = __ldg((const float4*)(A + (size_t)gm * DC) + kc * 16 + k4);
                if (AFF) {
                    float4 a = *((const float4*)g_aff + kc * 16 + k4);
                    float4 c = *((const float4*)g_aff + DC / 4 + kc * 16 + k4);
                    v.x = fmaxf(fmaf(a.x, v.x, c.x), 0.f);
                    v.y = fmaxf(fmaf(a.y, v.y, c.y), 0.f);
                    v.z = fmaxf(fmaf(a.z, v.z, c.z), 0.f);
                    v.w = fmaxf(fmaf(a.w, v.w, c.w), 0.f);
                }
            }
            uint32_t* ph = sAh + m * SAP + k4 * 4;
            uint32_t* pl = sAl + m * SAP + k4 * 4;
            uint32_t hx = f2tf(v.x), hy = f2tf(v.y), hz = f2tf(v.z), hw = f2tf(v.w);
            ph[0] = hx; ph[1] = hy; ph[2] = hz; ph[3] = hw;
            pl[0] = f2tf(v.x - __uint_as_float(hx));
            pl[1] = f2tf(v.y - __uint_as_float(hy));
            pl[2] = f2tf(v.z - __uint_as_float(hz));
            pl[3] = f2tf(v.w - __uint_as_float(hw));
        }
        __syncthreads();

        #pragma unroll
        for (int ks = 0; ks < 8; ks++) {
            const int k0 = ks * 8;
            uint32_t ah[2][4], al[2][4];
            #pragma unroll
            for (int mi = 0; mi < 2; mi++) {
                const int ro = (rm + mi * 16 + grp) * SAP + k0 + qid;
                ah[mi][0] = sAh[ro];
                ah[mi][1] = sAh[ro + 8 * SAP];
                ah[mi][2] = sAh[ro + 4];
                ah[mi][3] = sAh[ro + 8 * SAP + 4];
                al[mi][0] = sAl[ro];
                al[mi][1] = sAl[ro + 8 * SAP];
                al[mi][2] = sAl[ro + 4];
                al[mi][3] = sAl[ro + 8 * SAP + 4];
            }
            #pragma unroll
            for (int nj = 0; nj < 8; nj++) {
                const int co = (cn + nj * 8 + grp) * SAP + k0 + qid;
                uint32_t bh0 = sBh[co], bh1 = sBh[co + 4];
                uint32_t bl0 = sBl[co], bl1 = sBl[co + 4];
                #pragma unroll
                for (int mi = 0; mi < 2; mi++) {
                    asm volatile(
                        "mma.sync.aligned.m16n8k8.row.col.f32.tf32.tf32.f32 "
                        "{%0,%1,%2,%3}, {%4,%5,%6,%7}, {%8,%9}, {%0,%1,%2,%3};"
                        : "+f"(acc[mi][nj][0]), "+f"(acc[mi][nj][1]),
                          "+f"(acc[mi][nj][2]), "+f"(acc[mi][nj][3])
                        : "r"(ah[mi][0]), "r"(ah[mi][1]), "r"(ah[mi][2]), "r"(ah[mi][3]),
                          "r"(bh0), "r"(bh1));
                    asm volatile(
                        "mma.sync.aligned.m16n8k8.row.col.f32.tf32.tf32.f32 "
                        "{%0,%1,%2,%3}, {%4,%5,%6,%7}, {%8,%9}, {%0,%1,%2,%3};"
                        : "+f"(acc[mi][nj][0]), "+f"(acc[mi][nj][1]),
                          "+f"(acc[mi][nj][2]), "+f"(acc[mi][nj][3])
                        : "r"(ah[mi][0]), "r"(ah[mi][1]), "r"(ah[mi][2]), "r"(ah[mi][3]),
                          "r"(bl0), "r"(bl1));
                    asm volatile(
                        "mma.sync.aligned.m16n8k8.row.col.f32.tf32.tf32.f32 "
                        "{%0,%1,%2,%3}, {%4,%5,%6,%7}, {%8,%9}, {%0,%1,%2,%3};"
                        : "+f"(acc[mi][nj][0]), "+f"(acc[mi][nj][1]),
                          "+f"(acc[mi][nj][2]), "+f"(acc[mi][nj][3])
                        : "r"(al[mi][0]), "r"(al[mi][1]), "r"(al[mi][2]), "r"(al[mi][3]),
                          "r"(bh0), "r"(bh1));
                }
            }
        }
        __syncthreads();
    }

    // ---- epilogue: bias, store, per-channel stats ----
    float csum[16], csq[16];
    #pragma unroll
    for (int j = 0; j < 16; j++) { csum[j] = 0.f; csq[j] = 0.f; }

    #pragma unroll
    for (int nj = 0; nj < 8; nj++) {
        const int col = cn + nj * 8 + qid * 2;
        const float bx = __ldg(bias + col);
        const float by = __ldg(bias + col + 1);
        #pragma unroll
        for (int mi = 0; mi < 2; mi++) {
            int row0 = blockRow + rm + mi * 16 + grp;
            int row1 = row0 + 8;
            float v00 = acc[mi][nj][0] + bx, v01 = acc[mi][nj][1] + by;
            float v10 = acc[mi][nj][2] + bx, v11 = acc[mi][nj][3] + by;
            if (row0 < nrows) {
                *(float2*)(out + (size_t)row0 * DC + col) = make_float2(v00, v01);
                csum[nj * 2]     += v00; csq[nj * 2]     += v00 * v00;
                csum[nj * 2 + 1] += v01; csq[nj * 2 + 1] += v01 * v01;
            }
            if (row1 < nrows) {
                *(float2*)(out + (size_t)row1 * DC + col) = make_float2(v10, v11);
                csum[nj * 2]     += v10; csq[nj * 2]     += v10 * v10;
                csum[nj * 2 + 1] += v11; csq[nj * 2 + 1] += v11 * v11;
            }
        }
    }
    #pragma unroll
    for (int nj = 0; nj < 8; nj++) {
        const int col = cn + nj * 8 + qid * 2;
        atomicAdd(&sSum[col],     csum[nj * 2]);
        atomicAdd(&sSq [col],     csq [nj * 2]);
        atomicAdd(&sSum[col + 1], csum[nj * 2 + 1]);
        atomicAdd(&sSq [col + 1], csq [nj * 2 + 1]);
    }
    __syncthreads();
    if (t < DC) {
        atomicAdd(&g_stats[t],      sSum[t]);
        atomicAdd(&g_stats[DC + t], sSq[t]);
    }
}

// ---------------- BN stats -> affine; reset stats ----------------------------
__global__ void k_bn(const float* __restrict__ gamma, const float* __restrict__ beta)
{
    int c = threadIdx.x;
    float s  = g_stats[c];
    float sq = g_stats[DC + c];
    const float inv_n = 1.f / (float)NN;
    float mu  = s * inv_n;
    float var = fmaxf(sq * inv_n - mu * mu, 0.f);
    float a = __ldg(gamma + c) * rsqrtf(var + 1e-5f);
    g_aff[c]      = a;
    g_aff[DC + c] = __ldg(beta + c) - mu * a;
    g_stats[c]      = 0.f;
    g_stats[DC + c] = 0.f;
}

// ---------------- launcher ----------------------------------------------------
extern "C" void kernel_launch(void* const* d_in, const int* in_sizes, int n_in,
                              void* d_out, int out_size)
{
    const float* x   = (const float*)d_in[0];
    const int*   ei  = (const int*)  d_in[1];
    const float* W1  = (const float*)d_in[4];
    const float* b1  = (const float*)d_in[5];
    const float* g1  = (const float*)d_in[6];
    const float* be1 = (const float*)d_in[7];
    const float* W2  = (const float*)d_in[8];
    const float* b2  = (const float*)d_in[9];
    const float* g2  = (const float*)d_in[10];
    const float* be2 = (const float*)d_in[11];
    float* out = (float*)d_out;

    float *zp, *t1p, *t2p;
    cudaGetSymbolAddress((void**)&zp,  g_z);
    cudaGetSymbolAddress((void**)&t1p, g_t1);
    cudaGetSymbolAddress((void**)&t2p, g_t2);

    const size_t SMEM = (size_t)(4 * 128 * SAP + 2 * DC) * sizeof(float);
    cudaFuncSetAttribute(k_gemm_tc<false>, cudaFuncAttributeMaxDynamicSharedMemorySize, (int)SMEM);
    cudaFuncSetAttribute(k_gemm_tc<true>,  cudaFuncAttributeMaxDynamicSharedMemorySize, (int)SMEM);

    const int AFF_BLOCKS  = (NN * DC / 4 + 255) / 256;
    const int SC_BLOCKS   = (NE * 32 + 255) / 256;
    const int GEMM_BLOCKS = (NN + 127) / 128;

    k_zero_stats<<<1, 256>>>();

    const float* h = x;
    for (int l = 0; l < NL; l++) {
        if (l == 0) {
            k_affine<false><<<AFF_BLOCKS, 256>>>(h, zp, 0);
            k_scatter<false><<<SC_BLOCKS, 256>>>(h, ei, 0);
        } else {
            k_affine<true><<<AFF_BLOCKS, 256>>>(h, zp, 1);
            k_scatter<true><<<SC_BLOCKS, 256>>>(h, ei, 1);
        }
        k_gemm_tc<false><<<GEMM_BLOCKS, 256, SMEM>>>(zp, W1 + l * DC * DC, b1 + l * DC, t1p, NN);
        k_bn<<<1, DC>>>(g1 + l * DC, be1 + l * DC);
        k_gemm_tc<true><<<GEMM_BLOCKS, 256, SMEM>>>(t1p, W2 + l * DC * DC, b2 + l * DC, t2p, NN);
        k_bn<<<1, DC>>>(g2 + l * DC, be2 + l * DC);
        h = t2p;
    }
    k_affine<true><<<AFF_BLOCKS, 256>>>(t2p, out, 0);
}

// round 4
// speedup vs baseline: 2.9450x; 2.9450x over previous
#include <cuda_runtime.h>
#include <cstdint>

#define NN 100000
#define NE 1600000
#define DC 128
#define NL 3
#define SCAN_T 1024
#define SEG ((NN + SCAN_T - 1) / SCAN_T)

// ---------------- scratch (device globals; no allocations allowed) ----------
__device__ float g_z [(size_t)NN * DC];
__device__ float g_t1[(size_t)NN * DC];
__device__ float g_t2[(size_t)NN * DC];
__device__ float g_stats[2 * DC];
__device__ float g_aff [2 * DC];
__device__ int   g_deg[NN];
__device__ int   g_pos[NN];
__device__ int   g_off[NN + 1];
__device__ int   g_csr[NE];

// ---------------- tiny utility kernels --------------------------------------
__global__ void k_zero_stats() { g_stats[threadIdx.x] = 0.f; }

__global__ void k_zero_csr()
{
    int i = blockIdx.x * blockDim.x + threadIdx.x;
    if (i < NN) { g_deg[i] = 0; g_pos[i] = 0; }
}

// out[i] = relu?(a*in+c) elementwise (final output only)
__global__ void k_affine(const float* __restrict__ in, float* __restrict__ out)
{
    int i = blockIdx.x * blockDim.x + threadIdx.x;
    const int n4 = NN * DC / 4;
    if (i >= n4) return;
    float4 v = __ldg((const float4*)in + i);
    int c4 = i & (DC / 4 - 1);
    float4 a = *((const float4*)g_aff + c4);
    float4 c = *((const float4*)g_aff + DC / 4 + c4);
    v.x = fmaf(a.x, v.x, c.x);
    v.y = fmaf(a.y, v.y, c.y);
    v.z = fmaf(a.z, v.z, c.z);
    v.w = fmaf(a.w, v.w, c.w);
    ((float4*)out)[i] = v;
}

// ---------------- CSR build ---------------------------------------------------
__global__ void k_hist(const int* __restrict__ ei)
{
    int e = blockIdx.x * blockDim.x + threadIdx.x;
    if (e >= NE) return;
    atomicAdd(&g_deg[__ldg(ei + NE + e)], 1);
}

// single-block exclusive scan over g_deg -> g_off
__global__ void k_scan()
{
    __shared__ int ss[SCAN_T];
    const int t = threadIdx.x;
    const int base = t * SEG;
    int sum = 0;
    #pragma unroll 4
    for (int i = 0; i < SEG; i++) {
        int idx = base + i;
        if (idx < NN) sum += g_deg[idx];
    }
    ss[t] = sum;
    __syncthreads();
    #pragma unroll
    for (int off = 1; off < SCAN_T; off <<= 1) {
        int v = ss[t];
        int add = (t >= off) ? ss[t - off] : 0;
        __syncthreads();
        ss[t] = v + add;
        __syncthreads();
    }
    int running = (t > 0) ? ss[t - 1] : 0;   // exclusive prefix
    #pragma unroll 4
    for (int i = 0; i < SEG; i++) {
        int idx = base + i;
        if (idx < NN) {
            g_off[idx] = running;
            running += g_deg[idx];
        }
    }
    if (t == 0) g_off[NN] = NE;
}

__global__ void k_fill(const int* __restrict__ ei)
{
    int e = blockIdx.x * blockDim.x + threadIdx.x;
    if (e >= NE) return;
    int src = __ldg(ei + e);
    int dst = __ldg(ei + NE + e);
    int idx = g_off[dst] + atomicAdd(&g_pos[dst], 1);
    g_csr[idx] = src;
}

// ---------------- CSR aggregation: z[n] = f(h[n]) + sum_{s in N(n)} f(h[s]) ---
// warp per node, lane covers 4 channels; BN affine(+relu) fused into reads.
template<bool AFF>
__global__ void k_aggr(const float* __restrict__ h, int relu)
{
    int gt = blockIdx.x * blockDim.x + threadIdx.x;
    int n = gt >> 5;
    int lane = gt & 31;
    if (n >= NN) return;

    float4 a, c;
    if (AFF) {
        a = *((const float4*)g_aff + lane);
        c = *((const float4*)g_aff + DC / 4 + lane);
    }

    auto fetch = [&](int s) -> float4 {
        float4 v = __ldg((const float4*)(h + (size_t)s * DC) + lane);
        if (AFF) {
            v.x = fmaf(a.x, v.x, c.x);
            v.y = fmaf(a.y, v.y, c.y);
            v.z = fmaf(a.z, v.z, c.z);
            v.w = fmaf(a.w, v.w, c.w);
            if (relu) {
                v.x = fmaxf(v.x, 0.f); v.y = fmaxf(v.y, 0.f);
                v.z = fmaxf(v.z, 0.f); v.w = fmaxf(v.w, 0.f);
            }
        }
        return v;
    };

    float4 acc = fetch(n);   // self term (eps = 0)

    const int i0 = __ldg(g_off + n);
    const int i1 = __ldg(g_off + n + 1);
    int s_cur = 0, s_nxt = 0;
    if (i0 < i1)     s_cur = __ldg(g_csr + i0);
    if (i0 + 1 < i1) s_nxt = __ldg(g_csr + i0 + 1);
    for (int i = i0; i < i1; i++) {
        int s = s_cur;
        s_cur = s_nxt;
        if (i + 2 < i1) s_nxt = __ldg(g_csr + i + 2);
        float4 v = fetch(s);
        acc.x += v.x; acc.y += v.y; acc.z += v.z; acc.w += v.w;
    }
    *((float4*)(g_z + (size_t)n * DC) + lane) = acc;
}

// ---------------- fp32 FFMA GEMM + bias + BN-stats, 2 CTAs/SM ----------------
// out[m][n] = sum_k f(A[m][k]) * W[k][n] + bias[n]; K chunked 2x64 to halve smem.
// 256 thr, 128x128 tile, 8x8 thread tile.
#define KCH 64
#define SAP 68   // A pitch (floats)

template<bool AFF>
__global__ void __launch_bounds__(256, 2)
k_gemm(const float* __restrict__ A, const float* __restrict__ W,
       const float* __restrict__ bias, float* __restrict__ out, int nrows)
{
    extern __shared__ float sm[];
    float* sA   = sm;                    // [128][SAP]  (chunk-local k)
    float* sB   = sm + 128 * SAP;        // [KCH][128]
    float* sSum = sB + KCH * 128;        // [128]
    float* sSq  = sSum + DC;             // [128]

    const int t = threadIdx.x;
    const int blockRow = blockIdx.x * 128;

    if (t < DC) { sSum[t] = 0.f; sSq[t] = 0.f; }

    const int tx = t & 15, ty = t >> 4;
    const int m0 = ty * 8, n0 = tx * 8;

    float acc[8][8];
    #pragma unroll
    for (int i = 0; i < 8; i++)
        #pragma unroll
        for (int j = 0; j < 8; j++)
            acc[i][j] = 0.f;

    for (int kc = 0; kc < 2; kc++) {
        // W chunk: rows [kc*64, kc*64+64), all 128 cols
        #pragma unroll
        for (int i = 0; i < 8; i++) {
            int idx = i * 256 + t;          // float4 idx over 64x128
            int kl  = idx >> 5;
            int n4  = idx & 31;
            float4 v = __ldg((const float4*)W + (kc * KCH + kl) * 32 + n4);
            *(float4*)(sB + kl * 128 + n4 * 4) = v;
        }
        // A chunk: 128 rows x 64 cols, fused affine+relu; zero-pad invalid rows
        #pragma unroll
        for (int i = 0; i < 8; i++) {
            int idx = i * 256 + t;          // float4 idx over 128x64
            int m   = idx >> 4;
            int k4  = idx & 15;
            int gm  = blockRow + m;
            float4 v = make_float4(0.f, 0.f, 0.f, 0.f);
            if (gm < nrows) {
                v = __ldg((const float4*)(A + (size_t)gm * DC) + kc * 16 + k4);
                if (AFF) {
                    float4 a = *((const float4*)g_aff + kc * 16 + k4);
                    float4 c = *((const float4*)g_aff + DC / 4 + kc * 16 + k4);
                    v.x = fmaxf(fmaf(a.x, v.x, c.x), 0.f);
                    v.y = fmaxf(fmaf(a.y, v.y, c.y), 0.f);
                    v.z = fmaxf(fmaf(a.z, v.z, c.z), 0.f);
                    v.w = fmaxf(fmaf(a.w, v.w, c.w), 0.f);
                }
            }
            *(float4*)(sA + m * SAP + k4 * 4) = v;
        }
        __syncthreads();

        #pragma unroll 2
        for (int k0 = 0; k0 < KCH; k0 += 4) {
            float4 av[8];
            #pragma unroll
            for (int i = 0; i < 8; i++)
                av[i] = *(const float4*)(sA + (m0 + i) * SAP + k0);
            #pragma unroll
            for (int kk = 0; kk < 4; kk++) {
                float4 b0 = *(const float4*)(sB + (k0 + kk) * 128 + n0);
                float4 b1 = *(const float4*)(sB + (k0 + kk) * 128 + n0 + 4);
                #pragma unroll
                for (int i = 0; i < 8; i++) {
                    float a = (kk == 0) ? av[i].x : (kk == 1) ? av[i].y
                            : (kk == 2) ? av[i].z : av[i].w;
                    acc[i][0] = fmaf(a, b0.x, acc[i][0]);
                    acc[i][1] = fmaf(a, b0.y, acc[i][1]);
                    acc[i][2] = fmaf(a, b0.z, acc[i][2]);
                    acc[i][3] = fmaf(a, b0.w, acc[i][3]);
                    acc[i][4] = fmaf(a, b1.x, acc[i][4]);
                    acc[i][5] = fmaf(a, b1.y, acc[i][5]);
                    acc[i][6] = fmaf(a, b1.z, acc[i][6]);
                    acc[i][7] = fmaf(a, b1.w, acc[i][7]);
                }
            }
        }
        __syncthreads();
    }

    // ---- epilogue: bias, store, per-channel stats ----
    float4 bv0 = __ldg((const float4*)(bias + n0));
    float4 bv1 = __ldg((const float4*)(bias + n0) + 1);
    float csum[8] = {0, 0, 0, 0, 0, 0, 0, 0};
    float csq [8] = {0, 0, 0, 0, 0, 0, 0, 0};
    #pragma unroll
    for (int i = 0; i < 8; i++) {
        int gm = blockRow + m0 + i;
        float v0 = acc[i][0] + bv0.x, v1 = acc[i][1] + bv0.y;
        float v2 = acc[i][2] + bv0.z, v3 = acc[i][3] + bv0.w;
        float v4 = acc[i][4] + bv1.x, v5 = acc[i][5] + bv1.y;
        float v6 = acc[i][6] + bv1.z, v7 = acc[i][7] + bv1.w;
        if (gm < nrows) {
            float* po = out + (size_t)gm * DC + n0;
            *(float4*)po       = make_float4(v0, v1, v2, v3);
            *(float4*)(po + 4) = make_float4(v4, v5, v6, v7);
            csum[0] += v0; csq[0] += v0 * v0;
            csum[1] += v1; csq[1] += v1 * v1;
            csum[2] += v2; csq[2] += v2 * v2;
            csum[3] += v3; csq[3] += v3 * v3;
            csum[4] += v4; csq[4] += v4 * v4;
            csum[5] += v5; csq[5] += v5 * v5;
            csum[6] += v6; csq[6] += v6 * v6;
            csum[7] += v7; csq[7] += v7 * v7;
        }
    }
    #pragma unroll
    for (int j = 0; j < 8; j++) {
        atomicAdd(&sSum[n0 + j], csum[j]);
        atomicAdd(&sSq [n0 + j], csq [j]);
    }
    __syncthreads();
    if (t < DC) {
        atomicAdd(&g_stats[t],      sSum[t]);
        atomicAdd(&g_stats[DC + t], sSq[t]);
    }
}

// ---------------- BN stats -> affine; reset stats ----------------------------
__global__ void k_bn(const float* __restrict__ gamma, const float* __restrict__ beta)
{
    int c = threadIdx.x;
    float s  = g_stats[c];
    float sq = g_stats[DC + c];
    const float inv_n = 1.f / (float)NN;
    float mu  = s * inv_n;
    float var = fmaxf(sq * inv_n - mu * mu, 0.f);
    float a = __ldg(gamma + c) * rsqrtf(var + 1e-5f);
    g_aff[c]      = a;
    g_aff[DC + c] = __ldg(beta + c) - mu * a;
    g_stats[c]      = 0.f;
    g_stats[DC + c] = 0.f;
}

// ---------------- launcher ----------------------------------------------------
extern "C" void kernel_launch(void* const* d_in, const int* in_sizes, int n_in,
                              void* d_out, int out_size)
{
    const float* x   = (const float*)d_in[0];
    const int*   ei  = (const int*)  d_in[1];
    const float* W1  = (const float*)d_in[4];
    const float* b1  = (const float*)d_in[5];
    const float* g1  = (const float*)d_in[6];
    const float* be1 = (const float*)d_in[7];
    const float* W2  = (const float*)d_in[8];
    const float* b2  = (const float*)d_in[9];
    const float* g2  = (const float*)d_in[10];
    const float* be2 = (const float*)d_in[11];
    float* out = (float*)d_out;

    float *zp, *t1p, *t2p;
    cudaGetSymbolAddress((void**)&zp,  g_z);
    cudaGetSymbolAddress((void**)&t1p, g_t1);
    cudaGetSymbolAddress((void**)&t2p, g_t2);

    const size_t SMEM = (size_t)(128 * SAP + KCH * 128 + 2 * DC) * sizeof(float);
    cudaFuncSetAttribute(k_gemm<false>, cudaFuncAttributeMaxDynamicSharedMemorySize, (int)SMEM);
    cudaFuncSetAttribute(k_gemm<true>,  cudaFuncAttributeMaxDynamicSharedMemorySize, (int)SMEM);

    const int AFF_BLOCKS  = (NN * DC / 4 + 255) / 256;
    const int E_BLOCKS    = (NE + 255) / 256;
    const int N_BLOCKS    = (NN + 255) / 256;
    const int AGG_BLOCKS  = (NN * 32 + 255) / 256;
    const int GEMM_BLOCKS = (NN + 127) / 128;

    // CSR build (once per launch; reused by all 3 layers)
    k_zero_stats<<<1, 256>>>();
    k_zero_csr<<<N_BLOCKS, 256>>>();
    k_hist<<<E_BLOCKS, 256>>>(ei);
    k_scan<<<1, SCAN_T>>>();
    k_fill<<<E_BLOCKS, 256>>>(ei);

    const float* h = x;
    for (int l = 0; l < NL; l++) {
        if (l == 0)
            k_aggr<false><<<AGG_BLOCKS, 256>>>(h, 0);
        else
            k_aggr<true><<<AGG_BLOCKS, 256>>>(h, 1);   // prev BN2+ReLU fused
        k_gemm<false><<<GEMM_BLOCKS, 256, SMEM>>>(zp, W1 + l * DC * DC, b1 + l * DC, t1p, NN);
        k_bn<<<1, DC>>>(g1 + l * DC, be1 + l * DC);
        k_gemm<true><<<GEMM_BLOCKS, 256, SMEM>>>(t1p, W2 + l * DC * DC, b2 + l * DC, t2p, NN);
        k_bn<<<1, DC>>>(g2 + l * DC, be2 + l * DC);
        h = t2p;
    }
    k_affine<<<AFF_BLOCKS, 256>>>(t2p, out);   // final BN2, no ReLU
}

// round 6
// speedup vs baseline: 3.2348x; 1.0984x over previous
#include <cuda_runtime.h>
#include <cstdint>

#define NN 100000
#define NE 1600000
#define DC 128
#define NL 3
#define NBLK 98          // ceil(NN/1024)

// ---------------- scratch (device globals; no allocations allowed) ----------
__device__ float g_z [(size_t)NN * DC];
__device__ float g_t1[(size_t)NN * DC];
__device__ float g_t2[(size_t)NN * DC];
__device__ float g_stats[2 * DC];
__device__ float g_aff [2 * DC];
__device__ int   g_deg[NN];
__device__ int   g_pos[NN];
__device__ int   g_off[NN + 1];
__device__ int   g_csr[NE];
__device__ int   g_bsum[NBLK];

// ---------------- tiny utility kernels --------------------------------------
__global__ void k_zero_stats() { g_stats[threadIdx.x] = 0.f; }

__global__ void k_zero_deg()
{
    int i = blockIdx.x * blockDim.x + threadIdx.x;
    if (i < NN) g_deg[i] = 0;
}

// final output: out = a*in + c (BN2 of last layer, no ReLU)
__global__ void k_affine(const float* __restrict__ in, float* __restrict__ out)
{
    int i = blockIdx.x * blockDim.x + threadIdx.x;
    const int n4 = NN * DC / 4;
    if (i >= n4) return;
    float4 v = __ldg((const float4*)in + i);
    int c4 = i & (DC / 4 - 1);
    float4 a = *((const float4*)g_aff + c4);
    float4 c = *((const float4*)g_aff + DC / 4 + c4);
    v.x = fmaf(a.x, v.x, c.x);
    v.y = fmaf(a.y, v.y, c.y);
    v.z = fmaf(a.z, v.z, c.z);
    v.w = fmaf(a.w, v.w, c.w);
    ((float4*)out)[i] = v;
}

// ---------------- CSR build ---------------------------------------------------
// 4 edges per thread (int4 loads); NE % 4 == 0.
__global__ void k_hist(const int* __restrict__ ei)
{
    int q = blockIdx.x * blockDim.x + threadIdx.x;
    if (q >= NE / 4) return;
    int4 d = __ldg((const int4*)(ei + NE) + q);
    atomicAdd(&g_deg[d.x], 1);
    atomicAdd(&g_deg[d.y], 1);
    atomicAdd(&g_deg[d.z], 1);
    atomicAdd(&g_deg[d.w], 1);
}

__global__ void k_scan1()
{
    __shared__ int ws[32];
    int t = threadIdx.x;
    int i = blockIdx.x * 1024 + t;
    int v = (i < NN) ? g_deg[i] : 0;
    #pragma unroll
    for (int d = 16; d; d >>= 1) v += __shfl_down_sync(0xFFFFFFFF, v, d);
    if ((t & 31) == 0) ws[t >> 5] = v;
    __syncthreads();
    if (t < 32) {
        int x = ws[t];
        #pragma unroll
        for (int d = 16; d; d >>= 1) x += __shfl_down_sync(0xFFFFFFFF, x, d);
        if (t == 0) g_bsum[blockIdx.x] = x;
    }
}

__global__ void k_scan2()
{
    __shared__ int s[128];
    int t = threadIdx.x;
    s[t] = (t < NBLK) ? g_bsum[t] : 0;
    __syncthreads();
    for (int off = 1; off < 128; off <<= 1) {
        int v = s[t];
        int a = (t >= off) ? s[t - off] : 0;
        __syncthreads();
        s[t] = v + a;
        __syncthreads();
    }
    if (t < NBLK) g_bsum[t] = (t > 0) ? s[t - 1] : 0;
}

__global__ void k_scan3()
{
    __shared__ int ws[32];
    int t = threadIdx.x;
    int lane = t & 31, wid = t >> 5;
    int i = blockIdx.x * 1024 + t;
    int v = (i < NN) ? g_deg[i] : 0;
    int incl = v;
    #pragma unroll
    for (int d = 1; d < 32; d <<= 1) {
        int n = __shfl_up_sync(0xFFFFFFFF, incl, d);
        if (lane >= d) incl += n;
    }
    if (lane == 31) ws[wid] = incl;
    __syncthreads();
    if (wid == 0) {
        int x = ws[lane];
        #pragma unroll
        for (int d = 1; d < 32; d <<= 1) {
            int n = __shfl_up_sync(0xFFFFFFFF, x, d);
            if (lane >= d) x += n;
        }
        ws[lane] = x;
    }
    __syncthreads();
    int excl = incl - v + ((wid > 0) ? ws[wid - 1] : 0) + g_bsum[blockIdx.x];
    if (i < NN) { g_off[i] = excl; g_pos[i] = excl; }
    if (i == 0) g_off[NN] = NE;
}

__global__ void k_fill(const int* __restrict__ ei)
{
    int q = blockIdx.x * blockDim.x + threadIdx.x;
    if (q >= NE / 4) return;
    int4 s = __ldg((const int4*)ei + q);
    int4 d = __ldg((const int4*)(ei + NE) + q);
    g_csr[atomicAdd(&g_pos[d.x], 1)] = s.x;
    g_csr[atomicAdd(&g_pos[d.y], 1)] = s.y;
    g_csr[atomicAdd(&g_pos[d.z], 1)] = s.z;
    g_csr[atomicAdd(&g_pos[d.w], 1)] = s.w;
}

// ---------------- CSR aggregation: z[n] = f(h[n]) + sum_{s in N(n)} f(h[s]) ---
template<bool AFF>
__global__ void k_aggr(const float* __restrict__ h, int relu)
{
    int gt = blockIdx.x * blockDim.x + threadIdx.x;
    int n = gt >> 5;
    int lane = gt & 31;
    if (n >= NN) return;

    float4 a, c;
    if (AFF) {
        a = *((const float4*)g_aff + lane);
        c = *((const float4*)g_aff + DC / 4 + lane);
    }

    auto fetch = [&](int s) -> float4 {
        float4 v = __ldg((const float4*)(h + (size_t)s * DC) + lane);
        if (AFF) {
            v.x = fmaf(a.x, v.x, c.x);
            v.y = fmaf(a.y, v.y, c.y);
            v.z = fmaf(a.z, v.z, c.z);
            v.w = fmaf(a.w, v.w, c.w);
            if (relu) {
                v.x = fmaxf(v.x, 0.f); v.y = fmaxf(v.y, 0.f);
                v.z = fmaxf(v.z, 0.f); v.w = fmaxf(v.w, 0.f);
            }
        }
        return v;
    };

    float4 acc = fetch(n);   // self term (eps = 0)

    const int i0 = __ldg(g_off + n);
    const int i1 = __ldg(g_off + n + 1);
    int s_cur = 0, s_nxt = 0;
    if (i0 < i1)     s_cur = __ldg(g_csr + i0);
    if (i0 + 1 < i1) s_nxt = __ldg(g_csr + i0 + 1);
    for (int i = i0; i < i1; i++) {
        int s = s_cur;
        s_cur = s_nxt;
        if (i + 2 < i1) s_nxt = __ldg(g_csr + i + 2);
        float4 v = fetch(s);
        acc.x += v.x; acc.y += v.y; acc.z += v.z; acc.w += v.w;
    }
    *((float4*)(g_z + (size_t)n * DC) + lane) = acc;
}

// ---------------- fp32 FFMA GEMM + bias + BN-stats, 2 CTAs/SM ----------------
// out[m][n] = sum_k f(A[m][k]) * W[k][n] + bias[n]; K chunked 2x64 to halve smem.
// 256 thr, 128x128 tile, 8x8 thread tile.
#define KCH 64
#define SAP 68   // A pitch (floats)

template<bool AFF>
__global__ void __launch_bounds__(256, 2)
k_gemm(const float* __restrict__ A, const float* __restrict__ W,
       const float* __restrict__ bias, float* __restrict__ out, int nrows)
{
    extern __shared__ float sm[];
    float* sA   = sm;                    // [128][SAP]  (chunk-local k)
    float* sB   = sm + 128 * SAP;        // [KCH][128]
    float* sSum = sB + KCH * 128;        // [128]
    float* sSq  = sSum + DC;             // [128]

    const int t = threadIdx.x;
    const int blockRow = blockIdx.x * 128;

    if (t < DC) { sSum[t] = 0.f; sSq[t] = 0.f; }

    const int tx = t & 15, ty = t >> 4;
    const int m0 = ty * 8, n0 = tx * 8;

    float acc[8][8];
    #pragma unroll
    for (int i = 0; i < 8; i++)
        #pragma unroll
        for (int j = 0; j < 8; j++)
            acc[i][j] = 0.f;

    for (int kc = 0; kc < 2; kc++) {
        // W chunk: rows [kc*64, kc*64+64), all 128 cols
        #pragma unroll
        for (int i = 0; i < 8; i++) {
            int idx = i * 256 + t;          // float4 idx over 64x128
            int kl  = idx >> 5;
            int n4  = idx & 31;
            float4 v = __ldg((const float4*)W + (kc * KCH + kl) * 32 + n4);
            *(float4*)(sB + kl * 128 + n4 * 4) = v;
        }
        // A chunk: 128 rows x 64 cols, fused affine+relu; zero-pad invalid rows
        #pragma unroll
        for (int i = 0; i < 8; i++) {
            int idx = i * 256 + t;          // float4 idx over 128x64
            int m   = idx >> 4;
            int k4  = idx & 15;
            int gm  = blockRow + m;
            float4 v = make_float4(0.f, 0.f, 0.f, 0.f);
            if (gm < nrows) {
                v = __ldg((const float4*)(A + (size_t)gm * DC) + kc * 16 + k4);
                if (AFF) {
                    float4 a = *((const float4*)g_aff + kc * 16 + k4);
                    float4 c = *((const float4*)g_aff + DC / 4 + kc * 16 + k4);
                    v.x = fmaxf(fmaf(a.x, v.x, c.x), 0.f);
                    v.y = fmaxf(fmaf(a.y, v.y, c.y), 0.f);
                    v.z = fmaxf(fmaf(a.z, v.z, c.z), 0.f);
                    v.w = fmaxf(fmaf(a.w, v.w, c.w), 0.f);
                }
            }
            *(float4*)(sA + m * SAP + k4 * 4) = v;
        }
        __syncthreads();

        #pragma unroll 2
        for (int k0 = 0; k0 < KCH; k0 += 4) {
            float4 av[8];
            #pragma unroll
            for (int i = 0; i < 8; i++)
                av[i] = *(const float4*)(sA + (m0 + i) * SAP + k0);
            #pragma unroll
            for (int kk = 0; kk < 4; kk++) {
                float4 b0 = *(const float4*)(sB + (k0 + kk) * 128 + n0);
                float4 b1 = *(const float4*)(sB + (k0 + kk) * 128 + n0 + 4);
                #pragma unroll
                for (int i = 0; i < 8; i++) {
                    float a = (kk == 0) ? av[i].x : (kk == 1) ? av[i].y
                            : (kk == 2) ? av[i].z : av[i].w;
                    acc[i][0] = fmaf(a, b0.x, acc[i][0]);
                    acc[i][1] = fmaf(a, b0.y, acc[i][1]);
                    acc[i][2] = fmaf(a, b0.z, acc[i][2]);
                    acc[i][3] = fmaf(a, b0.w, acc[i][3]);
                    acc[i][4] = fmaf(a, b1.x, acc[i][4]);
                    acc[i][5] = fmaf(a, b1.y, acc[i][5]);
                    acc[i][6] = fmaf(a, b1.z, acc[i][6]);
                    acc[i][7] = fmaf(a, b1.w, acc[i][7]);
                }
            }
        }
        __syncthreads();
    }

    // ---- epilogue: bias, store, per-channel stats ----
    float4 bv0 = __ldg((const float4*)(bias + n0));
    float4 bv1 = __ldg((const float4*)(bias + n0) + 1);
    float csum[8] = {0, 0, 0, 0, 0, 0, 0, 0};
    float csq [8] = {0, 0, 0, 0, 0, 0, 0, 0};
    #pragma unroll
    for (int i = 0; i < 8; i++) {
        int gm = blockRow + m0 + i;
        float v0 = acc[i][0] + bv0.x, v1 = acc[i][1] + bv0.y;
        float v2 = acc[i][2] + bv0.z, v3 = acc[i][3] + bv0.w;
        float v4 = acc[i][4] + bv1.x, v5 = acc[i][5] + bv1.y;
        float v6 = acc[i][6] + bv1.z, v7 = acc[i][7] + bv1.w;
        if (gm < nrows) {
            float* po = out + (size_t)gm * DC + n0;
            *(float4*)po       = make_float4(v0, v1, v2, v3);
            *(float4*)(po + 4) = make_float4(v4, v5, v6, v7);
            csum[0] += v0; csq[0] += v0 * v0;
            csum[1] += v1; csq[1] += v1 * v1;
            csum[2] += v2; csq[2] += v2 * v2;
            csum[3] += v3; csq[3] += v3 * v3;
            csum[4] += v4; csq[4] += v4 * v4;
            csum[5] += v5; csq[5] += v5 * v5;
            csum[6] += v6; csq[6] += v6 * v6;
            csum[7] += v7; csq[7] += v7 * v7;
        }
    }
    #pragma unroll
    for (int j = 0; j < 8; j++) {
        atomicAdd(&sSum[n0 + j], csum[j]);
        atomicAdd(&sSq [n0 + j], csq [j]);
    }
    __syncthreads();
    if (t < DC) {
        atomicAdd(&g_stats[t],      sSum[t]);
        atomicAdd(&g_stats[DC + t], sSq[t]);
    }
}

// ---------------- BN stats -> affine; reset stats ----------------------------
__global__ void k_bn(const float* __restrict__ gamma, const float* __restrict__ beta)
{
    int c = threadIdx.x;
    float s  = g_stats[c];
    float sq = g_stats[DC + c];
    const float inv_n = 1.f / (float)NN;
    float mu  = s * inv_n;
    float var = fmaxf(sq * inv_n - mu * mu, 0.f);
    float a = __ldg(gamma + c) * rsqrtf(var + 1e-5f);
    g_aff[c]      = a;
    g_aff[DC + c] = __ldg(beta + c) - mu * a;
    g_stats[c]      = 0.f;
    g_stats[DC + c] = 0.f;
}

// ---------------- launcher ----------------------------------------------------
extern "C" void kernel_launch(void* const* d_in, const int* in_sizes, int n_in,
                              void* d_out, int out_size)
{
    const float* x   = (const float*)d_in[0];
    const int*   ei  = (const int*)  d_in[1];
    const float* W1  = (const float*)d_in[4];
    const float* b1  = (const float*)d_in[5];
    const float* g1  = (const float*)d_in[6];
    const float* be1 = (const float*)d_in[7];
    const float* W2  = (const float*)d_in[8];
    const float* b2  = (const float*)d_in[9];
    const float* g2  = (const float*)d_in[10];
    const float* be2 = (const float*)d_in[11];
    float* out = (float*)d_out;

    float *zp, *t1p, *t2p;
    cudaGetSymbolAddress((void**)&zp,  g_z);
    cudaGetSymbolAddress((void**)&t1p, g_t1);
    cudaGetSymbolAddress((void**)&t2p, g_t2);

    const size_t SMEM = (size_t)(128 * SAP + KCH * 128 + 2 * DC) * sizeof(float);
    cudaFuncSetAttribute(k_gemm<false>, cudaFuncAttributeMaxDynamicSharedMemorySize, (int)SMEM);
    cudaFuncSetAttribute(k_gemm<true>,  cudaFuncAttributeMaxDynamicSharedMemorySize, (int)SMEM);

    const int AFF_BLOCKS  = (NN * DC / 4 + 255) / 256;
    const int E4_BLOCKS   = (NE / 4 + 255) / 256;
    const int N_BLOCKS    = (NN + 255) / 256;
    const int AGG_BLOCKS  = (NN * 32 + 255) / 256;
    const int GEMM_BLOCKS = (NN + 127) / 128;

    // CSR build (every launch; deterministic)
    k_zero_stats<<<1, 256>>>();
    k_zero_deg<<<N_BLOCKS, 256>>>();
    k_hist<<<E4_BLOCKS, 256>>>(ei);
    k_scan1<<<NBLK, 1024>>>();
    k_scan2<<<1, 128>>>();
    k_scan3<<<NBLK, 1024>>>();
    k_fill<<<E4_BLOCKS, 256>>>(ei);

    const float* h = x;
    for (int l = 0; l < NL; l++) {
        if (l == 0)
            k_aggr<false><<<AGG_BLOCKS, 256>>>(h, 0);
        else
            k_aggr<true><<<AGG_BLOCKS, 256>>>(h, 1);   // prev BN2+ReLU fused
        k_gemm<false><<<GEMM_BLOCKS, 256, SMEM>>>(zp, W1 + l * DC * DC, b1 + l * DC, t1p, NN);
        k_bn<<<1, DC>>>(g1 + l * DC, be1 + l * DC);
        k_gemm<true><<<GEMM_BLOCKS, 256, SMEM>>>(t1p, W2 + l * DC * DC, b2 + l * DC, t2p, NN);
        k_bn<<<1, DC>>>(g2 + l * DC, be2 + l * DC);
        h = t2p;
    }
    k_affine<<<AFF_BLOCKS, 256>>>(t2p, out);   // final BN2, no ReLU
}